// round 16
// baseline (speedup 1.0000x reference)
#include <cuda_runtime.h>
#include <cuda_fp16.h>
#include <cstdint>
#include <math.h>

// Problem constants: B=8, T=2048, D=2048, K=64
#define NROWS 16384
#define DDIM  2048
#define KDIM  64
#define THRESH 0.005f

// Scratch (allocation-free __device__ globals)
__device__ unsigned g_pH[KDIM * (DDIM / 2)];   // f16x2(p[2i], p[2i+1]) per k
__device__ float    g_pF[KDIM * DDIM];         // fp32 softmax(w) transposed [k][d]
__device__ float    g_nT[KDIM * DDIM];         // min-max normalized w cols, [k][d]
__device__ int      g_e[NROWS];                // argmax k (bits0..5) | neg (bit6)
__device__ int      g_done[128];               // per-CTA publish flags

// ---------------------------------------------------------------------------
// helpers
// ---------------------------------------------------------------------------
__device__ __forceinline__ unsigned smem_u32(const void* p) {
    return (unsigned)__cvta_generic_to_shared(p);
}
__device__ __forceinline__ void cp16(void* dst, const void* src) {
    asm volatile("cp.async.cg.shared.global [%0], [%1], 16;\n"
                 :: "r"(smem_u32(dst)), "l"(src));
}
// m16n8k16 fp16 mma, fp32 acc, D += A*B (baseline PTX, sm_80+)
__device__ __forceinline__ void mma16(float* d, const unsigned* a, const unsigned* b) {
    asm volatile(
        "mma.sync.aligned.m16n8k16.row.col.f32.f16.f16.f32 "
        "{%0,%1,%2,%3}, {%4,%5,%6,%7}, {%8,%9}, {%0,%1,%2,%3};"
        : "+f"(d[0]), "+f"(d[1]), "+f"(d[2]), "+f"(d[3])
        : "r"(a[0]), "r"(a[1]), "r"(a[2]), "r"(a[3]), "r"(b[0]), "r"(b[1]));
}

// ---------------------------------------------------------------------------
// Kernel 1a: softmax of w rows (over K) in fp32; write fp32 transposed g_pF
// and fp16-hi packed g_pH. One warp per d-PAIR, 2 k per lane.
// ---------------------------------------------------------------------------
__global__ void prep_softmax(const float* __restrict__ w) {
    int gw = (blockIdx.x * blockDim.x + threadIdx.x) >> 5;   // d-pair id
    if (gw >= DDIM / 2) return;
    int lane = threadIdx.x & 31;
    int d0 = gw * 2, d1 = d0 + 1;
    float a0 = w[d0 * KDIM + lane], a1 = w[d0 * KDIM + lane + 32];
    float b0 = w[d1 * KDIM + lane], b1 = w[d1 * KDIM + lane + 32];
    float m0 = fmaxf(a0, a1), m1 = fmaxf(b0, b1);
#pragma unroll
    for (int off = 16; off; off >>= 1) {
        m0 = fmaxf(m0, __shfl_xor_sync(0xffffffffu, m0, off));
        m1 = fmaxf(m1, __shfl_xor_sync(0xffffffffu, m1, off));
    }
    float ea0 = expf(a0 - m0), ea1 = expf(a1 - m0);
    float eb0 = expf(b0 - m1), eb1 = expf(b1 - m1);
    float s0 = ea0 + ea1, s1 = eb0 + eb1;
#pragma unroll
    for (int off = 16; off; off >>= 1) {
        s0 += __shfl_xor_sync(0xffffffffu, s0, off);
        s1 += __shfl_xor_sync(0xffffffffu, s1, off);
    }
    float r0 = 1.f / s0, r1 = 1.f / s1;
#pragma unroll
    for (int half = 0; half < 2; half++) {
        int k = lane + 32 * half;
        float p0 = (half ? ea1 : ea0) * r0;
        float p1 = (half ? eb1 : eb0) * r1;
        g_pF[k * DDIM + d0] = p0;
        g_pF[k * DDIM + d1] = p1;
        __half2 hp = __floats2half2_rn(p0, p1);          // low = d0
        g_pH[k * (DDIM / 2) + gw] = *reinterpret_cast<unsigned*>(&hp);
    }
}

// ---------------------------------------------------------------------------
// Kernel 1b: per-column min/max of w -> g_nT[k][d]. 1024 threads per CTA.
// Block 0 resets the per-CTA done flags (graph-replay safe).
// ---------------------------------------------------------------------------
__global__ __launch_bounds__(1024) void prep_norm(const float* __restrict__ w) {
    const int k = blockIdx.x;
    const int tid = threadIdx.x;
    if (k == 0 && tid < 128) g_done[tid] = 0;
    float v0 = w[tid * KDIM + k];
    float v1 = w[(tid + 1024) * KDIM + k];
    float mn = fminf(v0, v1), mx = fmaxf(v0, v1);
    __shared__ float smn[1024], smx[1024];
    smn[tid] = mn; smx[tid] = mx;
    __syncthreads();
    for (int s = 512; s; s >>= 1) {
        if (tid < s) {
            smn[tid] = fminf(smn[tid], smn[tid + s]);
            smx[tid] = fmaxf(smx[tid], smx[tid + s]);
        }
        __syncthreads();
    }
    mn = smn[0]; mx = smx[0];
    float inv = 1.f / (mx - mn);
    g_nT[k * DDIM + tid]        = (v0 - mn) * inv;
    g_nT[k * DDIM + tid + 1024] = (v1 - mn) * inv;
}

// ---------------------------------------------------------------------------
// Kernel 2 (mega): score (hi-only fp16 mma) -> inline fixup -> publish e ->
// acquire neighbor e -> fused out pass. 128 CTAs (all co-resident), 256 thr.
// ---------------------------------------------------------------------------
#define XSTR 40                          // floats per x smem row
#define XB   (128 * XSTR * 4)            // 20480 B
#define PSTRU 20                         // uints per p smem row (16 data + 4 pad)
#define PB   (KDIM * PSTRU * 4)          // 5120 B
#define STG  (XB + PB)                   // 25600 B
#define SMEM_SZ (4 * STG)                // 102400 B dynamic

__global__ __launch_bounds__(256, 1) void mega_kernel(const float* __restrict__ x,
                                                      float* __restrict__ out) {
    extern __shared__ char sm[];
    __shared__ int se[128];                       // per-row e (k | neg<<6)
    __shared__ int sflag[128];                    // row flagged?
    __shared__ unsigned long long skey[128];      // fixup atomicMax keys
    __shared__ int spair[8192];                   // packed (row_local<<6)|k
    __shared__ int snf;                           // pair count
    __shared__ int s_eprev;                       // neighbor e

    const int tid = threadIdx.x;
    const int wid = tid >> 5, lane = tid & 31;
    const int lq = lane >> 2;            // 0..7
    const int lr = lane & 3;             // 0..3
    const int cta = blockIdx.x;
    const size_t r0 = (size_t)cta * 128;
    const float* xg = x + r0 * DDIM;

    if (tid == 0) snf = 0;
    if (tid < 128) sflag[tid] = 0;

    float acc[8][4];
#pragma unroll
    for (int nt = 0; nt < 8; nt++)
#pragma unroll
        for (int e = 0; e < 4; e++) acc[nt][e] = 0.f;

    auto prefetch = [&](int c) {
        char* base = sm + (size_t)(c & 3) * STG;
#pragma unroll
        for (int i = 0; i < 4; i++) {               // x: 128 rows x 32 floats
            int v = tid + 256 * i;
            int row = v >> 3, s = v & 7;
            cp16(base + row * (XSTR * 4) + s * 16,
                 xg + (size_t)row * DDIM + c * 32 + s * 4);
        }
        {                                           // p: 64 rows x 16 uints
            int k = tid >> 2, j = tid & 3;
            cp16(base + XB + k * (PSTRU * 4) + j * 16,
                 g_pH + (size_t)k * (DDIM / 2) + c * 16 + j * 4);
        }
        asm volatile("cp.async.commit_group;\n");
    };

    prefetch(0); prefetch(1); prefetch(2);

#pragma unroll 1
    for (int c = 0; c < 64; ++c) {
        if (c < 62)       asm volatile("cp.async.wait_group 2;\n");
        else if (c == 62) asm volatile("cp.async.wait_group 1;\n");
        else              asm volatile("cp.async.wait_group 0;\n");
        __syncthreads();
        if (c + 3 < 64) prefetch(c + 3);

        const char* base = sm + (size_t)(c & 3) * STG;
        const float* xs = (const float*)base;
        const unsigned* ps = (const unsigned*)(base + XB);

#pragma unroll
        for (int s = 0; s < 2; ++s) {               // two k16 steps per chunk
            unsigned ah[4];
#pragma unroll
            for (int pr = 0; pr < 4; pr++) {        // A: f32 pair -> fp16x2
                int row = wid * 16 + lq + (pr & 1) * 8;
                int dof = 16 * s + 2 * lr + (pr >> 1) * 8;
                float2 f = *reinterpret_cast<const float2*>(xs + row * XSTR + dof);
                __half2 h2 = __floats2half2_rn(f.x, f.y);
                ah[pr] = *reinterpret_cast<unsigned*>(&h2);
            }
            unsigned bh[8][2];
#pragma unroll
            for (int nt = 0; nt < 8; nt++) {        // B: plain f16x2 loads
                int k = nt * 8 + lq;
                bh[nt][0] = ps[k * PSTRU + 8 * s + lr];
                bh[nt][1] = ps[k * PSTRU + 8 * s + lr + 4];
            }
#pragma unroll
            for (int nt = 0; nt < 8; nt++)
                mma16(acc[nt], ah, bh[nt]);
        }
    }

    // ---- Score epilogue -> smem ------------------------------------------
#pragma unroll
    for (int h = 0; h < 2; h++) {
        float bv = -3.402823466e38f; int bk = 0;
#pragma unroll
        for (int nt = 0; nt < 8; nt++)
#pragma unroll
            for (int j = 0; j < 2; j++) {
                float v = acc[nt][h * 2 + j];
                int k = nt * 8 + 2 * lr + j;
                if (v > bv) { bv = v; bk = k; }
            }
        float s1 = bv;
#pragma unroll
        for (int off = 1; off <= 2; off <<= 1)
            s1 = fmaxf(s1, __shfl_xor_sync(0xffffffffu, s1, off));
        unsigned long long mask = 0ull;
#pragma unroll
        for (int nt = 0; nt < 8; nt++)
#pragma unroll
            for (int j = 0; j < 2; j++) {
                float v = acc[nt][h * 2 + j];
                int k = nt * 8 + 2 * lr + j;
                if (v > s1 - THRESH) mask |= (1ull << k);
            }
#pragma unroll
        for (int off = 1; off <= 2; off <<= 1) {
            unsigned lo = (unsigned)mask, hi = (unsigned)(mask >> 32);
            lo |= __shfl_xor_sync(0xffffffffu, lo, off);
            hi |= __shfl_xor_sync(0xffffffffu, hi, off);
            mask = ((unsigned long long)hi << 32) | lo;
        }
#pragma unroll
        for (int off = 1; off <= 2; off <<= 1) {
            float ov = __shfl_xor_sync(0xffffffffu, bv, off);
            int   ok = __shfl_xor_sync(0xffffffffu, bk, off);
            if (ov > bv || (ov == bv && ok < bk)) { bv = ov; bk = ok; }
        }
        if (lr == 0) {
            int rl = wid * 16 + h * 8 + lq;          // local row
            se[rl] = bk | (bv < 0.f ? 64 : 0);       // provisional
            int cnt = __popcll(mask);
            if (cnt > 1 || fabsf(s1) < THRESH) {
                sflag[rl] = 1;
                skey[rl] = 0ull;
                int base = atomicAdd(&snf, cnt);
                unsigned long long m = mask;
                for (int i = 0; i < cnt; i++) {
                    int k = __ffsll((long long)m) - 1;
                    m &= m - 1;
                    spair[base + i] = (rl << 6) | k;
                }
            }
        }
    }
    __syncthreads();

    // ---- Inline fixup: warp per pair, exact fp32 dots (x tile L2-warm) ---
    const int np = snf;
    for (int i = wid; i < np; i += 8) {
        const int pr = spair[i];
        const int rl = pr >> 6, k = pr & 63;
        const float4* xr = reinterpret_cast<const float4*>(xg + (size_t)rl * DDIM);
        const float4* pf = reinterpret_cast<const float4*>(g_pF + (size_t)k * DDIM);
        float s = 0.f;
#pragma unroll
        for (int j = 0; j < 16; j++) {
            float4 xv = xr[lane + 32 * j];
            float4 pv = pf[lane + 32 * j];
            s = fmaf(xv.x, pv.x, s);
            s = fmaf(xv.y, pv.y, s);
            s = fmaf(xv.z, pv.z, s);
            s = fmaf(xv.w, pv.w, s);
        }
#pragma unroll
        for (int off = 16; off; off >>= 1)
            s += __shfl_xor_sync(0xffffffffu, s, off);
        if (lane == 0) {
            unsigned b = __float_as_uint(s);
            if (b == 0x80000000u) b = 0u;            // canonicalize -0 -> +0
            unsigned u = (b & 0x80000000u) ? ~b : (b | 0x80000000u);
            unsigned long long key =
                ((unsigned long long)u << 32) | (unsigned)(63 - k);
            atomicMax(&skey[rl], key);
        }
    }
    __syncthreads();
    if (tid < 128 && sflag[tid]) {                   // decode winners
        const unsigned long long key = skey[tid];
        const int k = 63 - (int)(key & 63u);
        const bool neg = ((key >> 63) & 1ull) == 0ull;
        se[tid] = k | (neg ? 64 : 0);
    }
    __syncthreads();

    // ---- Publish e (release) ---------------------------------------------
    if (tid < 128) {
        g_e[r0 + tid] = se[tid];
        __threadfence();
    }
    __syncthreads();
    if (tid == 0) atomicExch(&g_done[cta], 1);

    // ---- Acquire neighbor e[r0-1] ----------------------------------------
    if (tid == 0) {
        if ((cta & 15) != 0) {                       // not a batch start
            while (atomicAdd(&g_done[cta - 1], 0) == 0) __nanosleep(64);
            __threadfence();
            s_eprev = g_e[r0 - 1];
        } else {
            s_eprev = -1;                            // t==0 row -> W = 0
        }
    }
    __syncthreads();
    const int e_prev = s_eprev;

    // ---- Fused out pass: out = x + x*W (x tile re-read, partially L2-hot)
    const float4* xr4 = reinterpret_cast<const float4*>(xg);
    float4* or4 = reinterpret_cast<float4*>(out + r0 * DDIM);
#pragma unroll 1
    for (int r = 127; r >= 0; --r) {
        const int e = (r == 0) ? e_prev : se[r - 1];
        const int idx0 = r * 512 + tid;
        if (e < 0) {
            or4[idx0] = xr4[idx0];
            or4[idx0 + 256] = xr4[idx0 + 256];
        } else {
            const float4* nr = reinterpret_cast<const float4*>(
                g_nT + (size_t)(e & 63) * DDIM);
            const bool neg = (e & 64) != 0;
#pragma unroll
            for (int it = 0; it < 2; ++it) {
                int i = idx0 + 256 * it;
                float4 xv = xr4[i];
                float4 nv = nr[tid + 256 * it];
                float wx = neg ? 1.f - nv.x : nv.x;
                float wy = neg ? 1.f - nv.y : nv.y;
                float wz = neg ? 1.f - nv.z : nv.z;
                float ww = neg ? 1.f - nv.w : nv.w;
                float4 o;
                o.x = fmaf(xv.x, wx, xv.x);
                o.y = fmaf(xv.y, wy, xv.y);
                o.z = fmaf(xv.z, wz, xv.z);
                o.w = fmaf(xv.w, ww, xv.w);
                or4[i] = o;
            }
        }
    }
}

// ---------------------------------------------------------------------------
extern "C" void kernel_launch(void* const* d_in, const int* in_sizes, int n_in,
                              void* d_out, int out_size) {
    const float* x = (const float*)d_in[0];
    const float* w = (const float*)d_in[1];
    if (n_in >= 2 && in_sizes[0] < in_sizes[1]) {
        const float* t = x; x = w; w = t;
    }
    cudaFuncSetAttribute(mega_kernel,
                         cudaFuncAttributeMaxDynamicSharedMemorySize, SMEM_SZ);
    prep_softmax<<<128, 256>>>(w);           // 1024 warps = DDIM/2 d-pairs
    prep_norm<<<KDIM, 1024>>>(w);
    mega_kernel<<<NROWS / 128, 256, SMEM_SZ>>>(x, (float*)d_out);
}

// round 17
// speedup vs baseline: 2.7377x; 2.7377x over previous
#include <cuda_runtime.h>
#include <cuda_fp16.h>
#include <cstdint>
#include <math.h>

// Problem constants: B=8, T=2048, D=2048, K=64
#define NROWS 16384
#define DDIM  2048
#define KDIM  64
#define THRESH 0.005f

// Scratch (allocation-free __device__ globals)
__device__ unsigned g_pH[KDIM * (DDIM / 2)];   // f16x2(p[2i], p[2i+1]) per k
__device__ float    g_pF[KDIM * DDIM];         // fp32 softmax(w) transposed [k][d]
__device__ float    g_nT[KDIM * DDIM];         // min-max normalized w cols, [k][d]
__device__ int      g_e[NROWS];                // k (b0..5) | neg (b6) | flagged (b7)
__device__ int      g_npair;                   // (row,k) candidate-pair count
__device__ int      g_pair[NROWS * KDIM];      // packed row*64+k candidates
__device__ unsigned long long g_pk[NROWS];     // packed (score,63-k) atomicMax keys

// ---------------------------------------------------------------------------
// helpers
// ---------------------------------------------------------------------------
__device__ __forceinline__ unsigned smem_u32(const void* p) {
    return (unsigned)__cvta_generic_to_shared(p);
}
__device__ __forceinline__ void cp16(void* dst, const void* src) {
    asm volatile("cp.async.cg.shared.global [%0], [%1], 16;\n"
                 :: "r"(smem_u32(dst)), "l"(src));
}
// m16n8k16 fp16 mma, fp32 acc, D += A*B (baseline PTX, sm_80+)
__device__ __forceinline__ void mma16(float* d, const unsigned* a, const unsigned* b) {
    asm volatile(
        "mma.sync.aligned.m16n8k16.row.col.f32.f16.f16.f32 "
        "{%0,%1,%2,%3}, {%4,%5,%6,%7}, {%8,%9}, {%0,%1,%2,%3};"
        : "+f"(d[0]), "+f"(d[1]), "+f"(d[2]), "+f"(d[3])
        : "r"(a[0]), "r"(a[1]), "r"(a[2]), "r"(a[3]), "r"(b[0]), "r"(b[1]));
}

// ---------------------------------------------------------------------------
// Kernel 1 (merged prep): CTAs 0..127 -> softmax of w rows (over K) in fp32,
// writing fp32 transposed g_pF and fp16 packed g_pH (one warp per d-pair).
// CTAs 128..191 -> per-column min/max of w into g_nT (one CTA per k).
// ---------------------------------------------------------------------------
__global__ __launch_bounds__(256) void prep_kernel(const float* __restrict__ w) {
    const int tid = threadIdx.x;
    if (blockIdx.x < 128) {
        int gw = (blockIdx.x * 256 + tid) >> 5;          // d-pair id
        int lane = tid & 31;
        int d0 = gw * 2, d1 = d0 + 1;
        float a0 = w[d0 * KDIM + lane], a1 = w[d0 * KDIM + lane + 32];
        float b0 = w[d1 * KDIM + lane], b1 = w[d1 * KDIM + lane + 32];
        float m0 = fmaxf(a0, a1), m1 = fmaxf(b0, b1);
#pragma unroll
        for (int off = 16; off; off >>= 1) {
            m0 = fmaxf(m0, __shfl_xor_sync(0xffffffffu, m0, off));
            m1 = fmaxf(m1, __shfl_xor_sync(0xffffffffu, m1, off));
        }
        float ea0 = expf(a0 - m0), ea1 = expf(a1 - m0);
        float eb0 = expf(b0 - m1), eb1 = expf(b1 - m1);
        float s0 = ea0 + ea1, s1 = eb0 + eb1;
#pragma unroll
        for (int off = 16; off; off >>= 1) {
            s0 += __shfl_xor_sync(0xffffffffu, s0, off);
            s1 += __shfl_xor_sync(0xffffffffu, s1, off);
        }
        float r0 = 1.f / s0, r1 = 1.f / s1;
#pragma unroll
        for (int half = 0; half < 2; half++) {
            int k = lane + 32 * half;
            float p0 = (half ? ea1 : ea0) * r0;
            float p1 = (half ? eb1 : eb0) * r1;
            g_pF[k * DDIM + d0] = p0;
            g_pF[k * DDIM + d1] = p1;
            __half2 hp = __floats2half2_rn(p0, p1);      // low = d0
            g_pH[k * (DDIM / 2) + gw] = *reinterpret_cast<unsigned*>(&hp);
        }
    } else {
        const int k = blockIdx.x - 128;
        if (k == 0 && tid == 0) g_npair = 0;
        float mn = 3.402823466e38f, mx = -3.402823466e38f;
        for (int d = tid; d < DDIM; d += 256) {
            float v = w[d * KDIM + k];
            mn = fminf(mn, v);
            mx = fmaxf(mx, v);
        }
        __shared__ float smn[256], smx[256];
        smn[tid] = mn; smx[tid] = mx;
        __syncthreads();
        for (int s = 128; s; s >>= 1) {
            if (tid < s) {
                smn[tid] = fminf(smn[tid], smn[tid + s]);
                smx[tid] = fmaxf(smx[tid], smx[tid + s]);
            }
            __syncthreads();
        }
        mn = smn[0]; mx = smx[0];
        float inv = 1.f / (mx - mn);
        for (int d = tid; d < DDIM; d += 256)
            g_nT[k * DDIM + d] = (w[d * KDIM + k] - mn) * inv;
    }
}

// ---------------------------------------------------------------------------
// Kernel 2: hi-only fp16 m16n8k16 scores + argmax + close-call flagging.
// 128 CTAs x (128 tok, 64 k). 8 warps, each 16 tok. 64 chunks of 32 dims.
// ---------------------------------------------------------------------------
#define XSTR 40                          // floats per x smem row
#define XB   (128 * XSTR * 4)            // 20480 B
#define PSTRU 20                         // uints per p smem row (16 data + 4 pad)
#define PB   (KDIM * PSTRU * 4)          // 5120 B
#define STG  (XB + PB)                   // 25600 B
#define SMEM_SZ (4 * STG)                // 102400 B

__global__ __launch_bounds__(256, 1) void score_kernel(const float* __restrict__ x) {
    extern __shared__ char sm[];
    const int tid = threadIdx.x;
    const int wid = tid >> 5, lane = tid & 31;
    const int lq = lane >> 2;            // 0..7
    const int lr = lane & 3;             // 0..3
    const float* xg = x + (size_t)blockIdx.x * 128 * DDIM;

    float acc[8][4];
#pragma unroll
    for (int nt = 0; nt < 8; nt++)
#pragma unroll
        for (int e = 0; e < 4; e++) acc[nt][e] = 0.f;

    auto prefetch = [&](int c) {
        char* base = sm + (size_t)(c & 3) * STG;
#pragma unroll
        for (int i = 0; i < 4; i++) {               // x: 128 rows x 32 floats
            int v = tid + 256 * i;
            int row = v >> 3, s = v & 7;
            cp16(base + row * (XSTR * 4) + s * 16,
                 xg + (size_t)row * DDIM + c * 32 + s * 4);
        }
        {                                           // p: 64 rows x 16 uints
            int k = tid >> 2, j = tid & 3;
            cp16(base + XB + k * (PSTRU * 4) + j * 16,
                 g_pH + (size_t)k * (DDIM / 2) + c * 16 + j * 4);
        }
        asm volatile("cp.async.commit_group;\n");
    };

    prefetch(0); prefetch(1); prefetch(2);

#pragma unroll 1
    for (int c = 0; c < 64; ++c) {
        if (c < 62)       asm volatile("cp.async.wait_group 2;\n");
        else if (c == 62) asm volatile("cp.async.wait_group 1;\n");
        else              asm volatile("cp.async.wait_group 0;\n");
        __syncthreads();
        if (c + 3 < 64) prefetch(c + 3);

        const char* base = sm + (size_t)(c & 3) * STG;
        const float* xs = (const float*)base;
        const unsigned* ps = (const unsigned*)(base + XB);

#pragma unroll
        for (int s = 0; s < 2; ++s) {               // two k16 steps per chunk
            unsigned ah[4];
#pragma unroll
            for (int pr = 0; pr < 4; pr++) {        // A: f32 pair -> fp16x2
                int row = wid * 16 + lq + (pr & 1) * 8;
                int dof = 16 * s + 2 * lr + (pr >> 1) * 8;
                float2 f = *reinterpret_cast<const float2*>(xs + row * XSTR + dof);
                __half2 h2 = __floats2half2_rn(f.x, f.y);
                ah[pr] = *reinterpret_cast<unsigned*>(&h2);
            }
            unsigned bh[8][2];
#pragma unroll
            for (int nt = 0; nt < 8; nt++) {        // B: plain f16x2 loads
                int k = nt * 8 + lq;
                bh[nt][0] = ps[k * PSTRU + 8 * s + lr];
                bh[nt][1] = ps[k * PSTRU + 8 * s + lr + 4];
            }
#pragma unroll
            for (int nt = 0; nt < 8; nt++)
                mma16(acc[nt], ah, bh[nt]);
        }
    }

    // Epilogue: rows wid*16 + h*8 + lq; cols nt*8 + 2*lr + j.
#pragma unroll
    for (int h = 0; h < 2; h++) {
        float bv = -3.402823466e38f; int bk = 0;
#pragma unroll
        for (int nt = 0; nt < 8; nt++)
#pragma unroll
            for (int j = 0; j < 2; j++) {
                float v = acc[nt][h * 2 + j];
                int k = nt * 8 + 2 * lr + j;
                if (v > bv) { bv = v; bk = k; }
            }
        float s1 = bv;
#pragma unroll
        for (int off = 1; off <= 2; off <<= 1)
            s1 = fmaxf(s1, __shfl_xor_sync(0xffffffffu, s1, off));
        unsigned long long mask = 0ull;
#pragma unroll
        for (int nt = 0; nt < 8; nt++)
#pragma unroll
            for (int j = 0; j < 2; j++) {
                float v = acc[nt][h * 2 + j];
                int k = nt * 8 + 2 * lr + j;
                if (v > s1 - THRESH) mask |= (1ull << k);
            }
#pragma unroll
        for (int off = 1; off <= 2; off <<= 1) {
            unsigned lo = (unsigned)mask, hi = (unsigned)(mask >> 32);
            lo |= __shfl_xor_sync(0xffffffffu, lo, off);
            hi |= __shfl_xor_sync(0xffffffffu, hi, off);
            mask = ((unsigned long long)hi << 32) | lo;
        }
#pragma unroll
        for (int off = 1; off <= 2; off <<= 1) {
            float ov = __shfl_xor_sync(0xffffffffu, bv, off);
            int   ok = __shfl_xor_sync(0xffffffffu, bk, off);
            if (ov > bv || (ov == bv && ok < bk)) { bv = ov; bk = ok; }
        }
        if (lr == 0) {
            int row = blockIdx.x * 128 + wid * 16 + h * 8 + lq;
            int cnt = __popcll(mask);
            bool flg = (cnt > 1 || fabsf(s1) < THRESH);
            g_e[row] = bk | (bv < 0.f ? 64 : 0) | (flg ? 128 : 0);
            if (flg) {
                g_pk[row] = 0ull;                   // reset packed key
                int base = atomicAdd(&g_npair, cnt);
                unsigned long long m = mask;
                for (int i = 0; i < cnt; i++) {
                    int k = __ffsll((long long)m) - 1;
                    m &= m - 1;
                    g_pair[base + i] = row * 64 + k;
                }
            }
        }
    }
}

// ---------------------------------------------------------------------------
// Kernel 3: fixup — one warp per (row,k) pair; exact fp32 dot; publish via
// atomicMax on order-preserving (score, 63-k) key. Sync-free, high MLP.
// ---------------------------------------------------------------------------
__global__ __launch_bounds__(256) void fixup_kernel(const float* __restrict__ x) {
    const int n = g_npair;
    const int gw = (blockIdx.x * blockDim.x + threadIdx.x) >> 5;
    const int nw = (gridDim.x * blockDim.x) >> 5;
    const int lane = threadIdx.x & 31;
    for (int i = gw; i < n; i += nw) {
        const int pr = g_pair[i];
        const int row = pr >> 6, k = pr & 63;
        const float4* xr = reinterpret_cast<const float4*>(x + (size_t)row * DDIM);
        const float4* pf = reinterpret_cast<const float4*>(g_pF + (size_t)k * DDIM);
        float s = 0.f;
#pragma unroll
        for (int j = 0; j < 16; j++) {
            float4 xv = xr[lane + 32 * j];
            float4 pv = pf[lane + 32 * j];
            s = fmaf(xv.x, pv.x, s);
            s = fmaf(xv.y, pv.y, s);
            s = fmaf(xv.z, pv.z, s);
            s = fmaf(xv.w, pv.w, s);
        }
#pragma unroll
        for (int off = 16; off; off >>= 1)
            s += __shfl_xor_sync(0xffffffffu, s, off);
        if (lane == 0) {
            unsigned b = __float_as_uint(s);
            if (b == 0x80000000u) b = 0u;            // canonicalize -0 -> +0
            unsigned u = (b & 0x80000000u) ? ~b : (b | 0x80000000u);
            unsigned long long key =
                ((unsigned long long)u << 32) | (unsigned)(63 - k);
            atomicMax(&g_pk[row], key);
        }
    }
}

// ---------------------------------------------------------------------------
// Kernel 4: out = x + x*W; decodes the fixup key inline for flagged rows.
// 1 row/CTA (measured ~37 us / 73% DRAM).
// ---------------------------------------------------------------------------
__global__ __launch_bounds__(256) void out_kernel(const float* __restrict__ x,
                                                  float* __restrict__ out) {
    const long row = blockIdx.x;
    const int tid = threadIdx.x;
    const float4* xr = reinterpret_cast<const float4*>(x + row * DDIM);
    float4* orow = reinterpret_cast<float4*>(out + row * DDIM);
    if ((row & 2047) == 0) {          // t == 0 -> W = 0
        orow[tid] = xr[tid];
        orow[tid + 256] = xr[tid + 256];
        return;
    }
    int e = g_e[row - 1];
    int k; bool neg;
    if (e & 128) {                    // flagged: decode exact winner
        const unsigned long long key = g_pk[row - 1];
        k = 63 - (int)(key & 63u);
        neg = ((key >> 63) & 1ull) == 0ull;
    } else {
        k = e & 63;
        neg = (e & 64) != 0;
    }
    const float4* nr = reinterpret_cast<const float4*>(g_nT + (size_t)k * DDIM);
#pragma unroll
    for (int it = 0; it < 2; ++it) {
        int i = tid + 256 * it;
        float4 xv = xr[i];
        float4 nv = nr[i];
        float wx = neg ? 1.f - nv.x : nv.x;
        float wy = neg ? 1.f - nv.y : nv.y;
        float wz = neg ? 1.f - nv.z : nv.z;
        float ww = neg ? 1.f - nv.w : nv.w;
        float4 o;
        o.x = fmaf(xv.x, wx, xv.x);
        o.y = fmaf(xv.y, wy, xv.y);
        o.z = fmaf(xv.z, wz, xv.z);
        o.w = fmaf(xv.w, ww, xv.w);
        orow[i] = o;
    }
}

// ---------------------------------------------------------------------------
extern "C" void kernel_launch(void* const* d_in, const int* in_sizes, int n_in,
                              void* d_out, int out_size) {
    const float* x = (const float*)d_in[0];
    const float* w = (const float*)d_in[1];
    if (n_in >= 2 && in_sizes[0] < in_sizes[1]) {
        const float* t = x; x = w; w = t;
    }
    cudaFuncSetAttribute(score_kernel,
                         cudaFuncAttributeMaxDynamicSharedMemorySize, SMEM_SZ);
    prep_kernel<<<192, 256>>>(w);            // softmax (128 CTAs) + norm (64 CTAs)
    score_kernel<<<NROWS / 128, 256, SMEM_SZ>>>(x);
    fixup_kernel<<<1024, 256>>>(x);
    out_kernel<<<NROWS, 256>>>(x, (float*)d_out);
}